// round 16
// baseline (speedup 1.0000x reference)
#include <cuda_runtime.h>
#include <cuda_fp16.h>
#include <math.h>

#define DIMC 768
#define NH 12
#define HD 64
#define NB 8
#define NT 1024
#define M_TOK (NB*NT)   // 8192
#define NTNT (NT*NT)

// ---- scratch (device globals: no allocations allowed) ----
__device__ __half g_xh[M_TOK*DIMC];            // x in fp16
__device__ __half g_wt[4*DIMC*DIMC];           // Wq,Wk,Wv,Wp fp16 TRANSPOSED [n][k]
__device__ __half g_q[NB*NH*NT*HD];            // [b,h,n,d] fp16, Q pre-scaled
__device__ __half g_k[NB*NH*NT*HD];            // [b,h,n,d] fp16
__device__ __half g_vt[NB*NH*HD*NT];           // [b,h,d,tok] fp16 (transposed V)
__device__ __half g_S[(size_t)NB*NH*NT*NT];    // scores / probs fp16 (in place)
__device__ __half g_Oh[(size_t)M_TOK*DIMC];    // [tok, dim] fp16

// ---------- helpers ----------
__device__ __forceinline__ void mma16h(float* d, unsigned a0, unsigned a1,
                                       unsigned a2, unsigned a3,
                                       unsigned b0, unsigned b1) {
    asm volatile(
        "mma.sync.aligned.m16n8k16.row.col.f32.f16.f16.f32 "
        "{%0,%1,%2,%3},{%4,%5,%6,%7},{%8,%9},{%0,%1,%2,%3};"
        : "+f"(d[0]), "+f"(d[1]), "+f"(d[2]), "+f"(d[3])
        : "r"(a0), "r"(a1), "r"(a2), "r"(a3), "r"(b0), "r"(b1));
}
__device__ __forceinline__ void ldsm4(unsigned& r0, unsigned& r1,
                                      unsigned& r2, unsigned& r3, unsigned sa) {
    asm volatile("ldmatrix.sync.aligned.m8n8.x4.shared.b16 {%0,%1,%2,%3}, [%4];"
                 : "=r"(r0), "=r"(r1), "=r"(r2), "=r"(r3) : "r"(sa));
}
__device__ __forceinline__ void cp16(void* s, const void* g) {
    unsigned sa = (unsigned)__cvta_generic_to_shared(s);
    asm volatile("cp.async.ca.shared.global [%0], [%1], 16;" :: "r"(sa), "l"(g));
}
#define CP_COMMIT asm volatile("cp.async.commit_group;")
#define CP_WAIT2  asm volatile("cp.async.wait_group 2;")
#define CP_WAIT0  asm volatile("cp.async.wait_group 0;")

// packed f32x2 (FFMA2) helpers — bit-identical to two scalar fmaf's
typedef unsigned long long ull;
__device__ __forceinline__ ull pack2(float lo, float hi) {
    ull r; asm("mov.b64 %0, {%1, %2};" : "=l"(r) : "f"(lo), "f"(hi)); return r;
}
__device__ __forceinline__ float2 unpack2(ull v) {
    float2 f; asm("mov.b64 {%0, %1}, %2;" : "=f"(f.x), "=f"(f.y) : "l"(v)); return f;
}
__device__ __forceinline__ void fma2(ull& d, ull a, ull b) {
    asm("fma.rn.f32x2 %0, %1, %2, %0;" : "+l"(d) : "l"(a), "l"(b));
}
__device__ __forceinline__ void mul2(ull& d, ull a, ull b) {
    asm("mul.rn.f32x2 %0, %1, %2;" : "=l"(d) : "l"(a), "l"(b));
}

// ============================================================
// conversion kernels
// ============================================================
__global__ __launch_bounds__(256) void conv_x(
    const float* __restrict__ x, __half* __restrict__ xh)
{
    int i = (blockIdx.x * 256 + threadIdx.x) * 4;
    float4 v = *(const float4*)&x[i];
    *(__half2*)&xh[i]     = __floats2half2_rn(v.x, v.y);
    *(__half2*)&xh[i + 2] = __floats2half2_rn(v.z, v.w);
}

// transpose+convert: out[n][k] = in[k][n], 32x32 tiles, z selects W
__global__ __launch_bounds__(256) void conv_wt(
    const float* __restrict__ Wq, const float* __restrict__ Wk,
    const float* __restrict__ Wv, const float* __restrict__ Wp,
    __half* __restrict__ Wt)
{
    __shared__ float t[32][33];
    int z = blockIdx.z;
    const float* W = (z == 0) ? Wq : (z == 1) ? Wk : (z == 2) ? Wv : Wp;
    __half* out = Wt + (size_t)z * DIMC * DIMC;
    int n0 = blockIdx.x * 32, k0 = blockIdx.y * 32;
    int tx = threadIdx.x & 31, ty = threadIdx.x >> 5;   // 32 x 8
#pragma unroll
    for (int i = ty; i < 32; i += 8)
        t[i][tx] = W[(size_t)(k0 + i) * DIMC + n0 + tx];
    __syncthreads();
#pragma unroll
    for (int i = ty; i < 32; i += 8)
        out[(size_t)(n0 + i) * DIMC + k0 + tx] = __float2half(t[tx][i]);
}

// ============================================================
// fp16 GEMM body: C[8192,768] = A @ Bm^T (Bm is [n][k] fp16).
// 128x128 tile, BK=32, 4-stage cp.async (wait 2), 256 thr,
// warp 64x32, ldmatrix fragments.
// MODE 1: head-split fp16 [b,h,n,d] (scale).
// MODE 2: transposed fp16 V [b,h,d,tok] via smem staging.
// MODE 3: plain fp32 out + bias.
// ============================================================
template<int MODE>
__device__ __forceinline__ void projh_body(
    const __half* __restrict__ A, const __half* __restrict__ Bm,
    float* __restrict__ Cf, __half* __restrict__ Ch,
    const float* __restrict__ bias, float scale)
{
    extern __shared__ float smf[];
    __half* As = (__half*)smf;        // [4][128][40]
    __half* Bs = As + 4 * 5120;       // [4][128][40]

    int tid = threadIdx.x, lane = tid & 31, wid = tid >> 5;
    int warp_m = wid & 1, warp_n = wid >> 1;
    int rowBase = blockIdx.y * 128, colBase = blockIdx.x * 128;
    int lr = lane >> 2, lc = lane & 3;
    int m0 = warp_m * 64, n0 = warp_n * 32;

    // ldmatrix per-lane addressing (half units)
    int aRow = lane & 15;
    int aK   = (lane >> 4) * 8;
    int mat  = lane >> 3;
    int bRow = (mat >> 1) * 8 + (lane & 7);
    int bK   = (mat & 1) * 8;

    const __half* Ap = A + (size_t)rowBase * DIMC;
    const __half* Bp = Bm + (size_t)colBase * DIMC;

#define QKV_LOAD(s, k0) do {                                            \
    __half* Ad = As + (s) * 5120;                                       \
    __half* Bd = Bs + (s) * 5120;                                       \
    _Pragma("unroll")                                                   \
    for (int i_ = 0; i_ < 2; i_++) {                                    \
        int t_ = tid + i_ * 256;                                        \
        int r_ = t_ >> 2, c_ = (t_ & 3) * 8;                            \
        cp16(&Ad[r_ * 40 + c_], Ap + (size_t)r_ * DIMC + (k0) + c_);    \
        cp16(&Bd[r_ * 40 + c_], Bp + (size_t)r_ * DIMC + (k0) + c_);    \
    }                                                                   \
    CP_COMMIT;                                                          \
} while (0)

    QKV_LOAD(0, 0);
    QKV_LOAD(1, 32);
    QKV_LOAD(2, 64);

    float acc[4][4][4] = {};
    const int NITER = DIMC / 32;   // 24
    for (int it = 0; it < NITER; it++) {
        CP_WAIT2;
        __syncthreads();
        int s = it % 4;
        unsigned qa = (unsigned)__cvta_generic_to_shared(As + s * 5120);
        unsigned qb = (unsigned)__cvta_generic_to_shared(Bs + s * 5120);
#pragma unroll
        for (int kk = 0; kk < 32; kk += 16) {
            unsigned a[4][4], b[4][2];
#pragma unroll
            for (int mi = 0; mi < 4; mi++) {
                unsigned ad = qa + ((m0 + mi * 16 + aRow) * 40 + kk + aK) * 2;
                ldsm4(a[mi][0], a[mi][1], a[mi][2], a[mi][3], ad);
            }
#pragma unroll
            for (int p = 0; p < 2; p++) {
                unsigned bd = qb + ((n0 + p * 16 + bRow) * 40 + kk + bK) * 2;
                ldsm4(b[2*p][0], b[2*p][1], b[2*p+1][0], b[2*p+1][1], bd);
            }
#pragma unroll
            for (int mi = 0; mi < 4; mi++)
#pragma unroll
                for (int ni = 0; ni < 4; ni++)
                    mma16h(acc[mi][ni], a[mi][0], a[mi][1], a[mi][2], a[mi][3],
                           b[ni][0], b[ni][1]);
        }
        __syncthreads();
        if (it + 3 < NITER) QKV_LOAD((it + 3) % 4, (it + 3) * 32);
        else CP_COMMIT;
    }
#undef QKV_LOAD

    if (MODE == 2) {
        // stage transposed fp16 tile: stg[local_col][local_row], stride 136
        __half* stg = (__half*)smf;   // 34816 B
#pragma unroll
        for (int mi = 0; mi < 4; mi++) {
#pragma unroll
            for (int ni = 0; ni < 4; ni++) {
                int col = n0 + ni * 8 + 2 * lc;
#pragma unroll
                for (int half_ = 0; half_ < 2; half_++) {
                    int row = m0 + mi * 16 + lr + half_ * 8;
                    stg[col * 136 + row]       = __float2half(acc[mi][ni][half_*2 + 0]);
                    stg[(col + 1) * 136 + row] = __float2half(acc[mi][ni][half_*2 + 1]);
                }
            }
        }
        __syncthreads();
        int b_ = rowBase >> 10;
        int rloc = rowBase & 1023;
        for (int t = tid; t < 128 * 16; t += 256) {
            int col = t >> 4;
            int r8 = (t & 15) * 8;
            int gcol = colBase + col;
            int hh = gcol >> 6, d = gcol & 63;
            size_t dst = ((size_t)(b_ * NH + hh) * HD + d) * NT + rloc + r8;
            *(uint4*)&Ch[dst] = *(const uint4*)&stg[col * 136 + r8];
        }
        return;
    }

#pragma unroll
    for (int mi = 0; mi < 4; mi++) {
#pragma unroll
        for (int ni = 0; ni < 4; ni++) {
            int col = colBase + n0 + ni * 8 + 2 * lc;
            float bv0 = 0.f, bv1 = 0.f;
            if (MODE == 3) { bv0 = bias[col]; bv1 = bias[col + 1]; }
#pragma unroll
            for (int half_ = 0; half_ < 2; half_++) {
                int row = rowBase + m0 + mi * 16 + lr + half_ * 8;
                if (MODE == 3) {
                    *(float2*)&Cf[(size_t)row * DIMC + col] =
                        make_float2(acc[mi][ni][half_*2 + 0] + bv0,
                                    acc[mi][ni][half_*2 + 1] + bv1);
                } else {    // MODE 1: fp16 head-split [b,h,n,d]
                    int b_ = row >> 10, rr = row & 1023;
                    int h = col >> 6, d = col & 63;
                    *(__half2*)&Ch[(((size_t)(b_ * NH + h) * NT + rr) * HD + d)] =
                        __floats2half2_rn(acc[mi][ni][half_*2 + 0] * scale,
                                          acc[mi][ni][half_*2 + 1] * scale);
                }
            }
        }
    }
}

__global__ __launch_bounds__(256, 2) void qkv_f16(
    const __half* __restrict__ xh, const __half* __restrict__ Wt,
    __half* __restrict__ q, __half* __restrict__ k, __half* __restrict__ vt)
{
    int z = blockIdx.z;
    const __half* Bm = Wt + (size_t)z * DIMC * DIMC;
    if (z == 0)      projh_body<1>(xh, Bm, nullptr, q, nullptr, 0.125f);
    else if (z == 1) projh_body<1>(xh, Bm, nullptr, k, nullptr, 1.0f);
    else             projh_body<2>(xh, Bm, nullptr, vt, nullptr, 1.0f);
}

__global__ __launch_bounds__(256, 2) void outproj_f16(
    const __half* __restrict__ Oh, const __half* __restrict__ Wt,
    float* __restrict__ C, const float* __restrict__ bias)
{
    projh_body<3>(Oh, Wt + (size_t)3 * DIMC * DIMC, C, nullptr, bias, 1.0f);
}

// ============================================================
// score_f16: per (b,h): S = Q(1024x64) @ K^T, fp16 MMA,
// SCALAR fragment loads (ldmatrix regressed at stride 72).
// 128x128 tile, whole K=64 in smem. Staged coalesced epilogue.
// ============================================================
__global__ __launch_bounds__(256, 2) void score_f16(
    const __half* __restrict__ Q, const __half* __restrict__ Kp,
    __half* __restrict__ S)
{
    extern __shared__ float smf[];
    __half* Qs = (__half*)smf;        // [128][72]
    __half* Ks = Qs + 128 * 72;       // [128][72]

    int bh = blockIdx.z;
    const __half* Qg = Q + (size_t)bh * NT * HD + (size_t)blockIdx.y * 128 * HD;
    const __half* Kg = Kp + (size_t)bh * NT * HD + (size_t)blockIdx.x * 128 * HD;

    int tid = threadIdx.x, lane = tid & 31, wid = tid >> 5;
    int lr = lane >> 2, lc = lane & 3;
    int warp_m = wid & 1, warp_n = wid >> 1;
    int m0 = warp_m * 64, n0 = warp_n * 32;

#pragma unroll
    for (int i = 0; i < 4; i++) {
        int t = tid + i * 256;
        int r = t >> 3, c = (t & 7) * 8;
        cp16(&Qs[r * 72 + c], Qg + (size_t)r * HD + c);
        cp16(&Ks[r * 72 + c], Kg + (size_t)r * HD + c);
    }
    CP_COMMIT;
    CP_WAIT0;
    __syncthreads();

    float acc[4][4][4] = {};
#pragma unroll
    for (int kk = 0; kk < 64; kk += 16) {
        unsigned a[4][4], b[4][2];
#pragma unroll
        for (int mi = 0; mi < 4; mi++) {
            int rb = (m0 + mi * 16 + lr) * 72 + kk + 2 * lc;
            a[mi][0] = *(const unsigned*)&Qs[rb];
            a[mi][1] = *(const unsigned*)&Qs[rb + 8 * 72];
            a[mi][2] = *(const unsigned*)&Qs[rb + 8];
            a[mi][3] = *(const unsigned*)&Qs[rb + 8 * 72 + 8];
        }
#pragma unroll
        for (int ni = 0; ni < 4; ni++) {
            int nb = (n0 + ni * 8 + lr) * 72 + kk + 2 * lc;
            b[ni][0] = *(const unsigned*)&Ks[nb];
            b[ni][1] = *(const unsigned*)&Ks[nb + 8];
        }
#pragma unroll
        for (int mi = 0; mi < 4; mi++)
#pragma unroll
            for (int ni = 0; ni < 4; ni++)
                mma16h(acc[mi][ni], a[mi][0], a[mi][1], a[mi][2], a[mi][3],
                       b[ni][0], b[ni][1]);
    }

    // stage fp16 tile in smem (reuse Qs/Ks), then coalesced uint4 flush
    __syncthreads();
    __half* stg = (__half*)smf;   // [128][136] halves = 34816 B
#pragma unroll
    for (int mi = 0; mi < 4; mi++) {
#pragma unroll
        for (int ni = 0; ni < 4; ni++) {
            int c = n0 + ni * 8 + 2 * lc;
#pragma unroll
            for (int half_ = 0; half_ < 2; half_++) {
                int r = m0 + mi * 16 + lr + half_ * 8;
                *(__half2*)&stg[r * 136 + c] =
                    __floats2half2_rn(acc[mi][ni][half_*2], acc[mi][ni][half_*2 + 1]);
            }
        }
    }
    __syncthreads();

    __half* Sg = S + (size_t)bh * NTNT +
                 (size_t)(blockIdx.y * 128) * NT + blockIdx.x * 128;
#pragma unroll
    for (int t = tid; t < 2048; t += 256) {
        int r = t >> 4, c8 = (t & 15) * 8;
        *(uint4*)&Sg[(size_t)r * NT + c8] = *(const uint4*)&stg[r * 136 + c8];
    }
}

// ============================================================
// softmax_mix_reg: register-resident talking-heads softmax,
// FFMA2 h-outer. 1 row/CTA, 256 thr, 4 j-cols/thread.
// ============================================================
__global__ __launch_bounds__(256, 2) void softmax_mix_reg(
    __half* __restrict__ S, const float* __restrict__ Wl,
    const float* __restrict__ bl, const float* __restrict__ Ww,
    const float* __restrict__ bw)
{
    __shared__ ull wl2[144], ww2[144];
    __shared__ float blv[12], bwv[12];
    __shared__ float red[8][12];

    int tid = threadIdx.x, lane = tid & 31, wid = tid >> 5;
    int i = blockIdx.x, b = blockIdx.y;
    if (tid < 144) {
        float a = Wl[tid]; wl2[tid] = pack2(a, a);
        float c = Ww[tid]; ww2[tid] = pack2(c, c);
    }
    if (tid < 12)  { blv[tid] = bl[tid]; bwv[tid] = bw[tid]; }
    __syncthreads();

    size_t rowbase = (size_t)b * NH * NTNT + (size_t)i * NT;
    int j0 = tid * 4;

    uint2 raw[12];
#pragma unroll
    for (int h = 0; h < 12; h++)
        raw[h] = *(const uint2*)&S[rowbase + (size_t)h * NTNT + j0];

    ull m2[12][2];
#pragma unroll
    for (int g = 0; g < 12; g++) {
        ull b2 = pack2(blv[g], blv[g]);
        m2[g][0] = b2; m2[g][1] = b2;
    }
#pragma unroll
    for (int h = 0; h < 12; h++) {
        float2 f0 = __half22float2(*(__half2*)&raw[h].x);
        float2 f1 = __half22float2(*(__half2*)&raw[h].y);
        ull s0 = pack2(f0.x, f0.y);
        ull s1 = pack2(f1.x, f1.y);
#pragma unroll
        for (int g = 0; g < 12; g++) {
            ull w = wl2[g * 12 + h];
            fma2(m2[g][0], w, s0);
            fma2(m2[g][1], w, s1);
        }
    }

#pragma unroll
    for (int h = 0; h < 12; h++) {
        float2 a0 = unpack2(m2[h][0]), a1 = unpack2(m2[h][1]);
        float a = fmaxf(fmaxf(a0.x, a0.y), fmaxf(a1.x, a1.y));
#pragma unroll
        for (int o = 16; o; o >>= 1) a = fmaxf(a, __shfl_xor_sync(0xffffffffu, a, o));
        if (lane == 0) red[wid][h] = a;
    }
    __syncthreads();
    float mxv[12];
#pragma unroll
    for (int h = 0; h < 12; h++) {
        float a = red[0][h];
#pragma unroll
        for (int w = 1; w < 8; w++) a = fmaxf(a, red[w][h]);
        mxv[h] = a;
    }
    __syncthreads();

#pragma unroll
    for (int h = 0; h < 12; h++) {
        float2 a0 = unpack2(m2[h][0]), a1 = unpack2(m2[h][1]);
        float e0 = __expf(a0.x - mxv[h]);
        float e1 = __expf(a0.y - mxv[h]);
        float e2 = __expf(a1.x - mxv[h]);
        float e3 = __expf(a1.y - mxv[h]);
        m2[h][0] = pack2(e0, e1);
        m2[h][1] = pack2(e2, e3);
        float s0 = (e0 + e1) + (e2 + e3);
#pragma unroll
        for (int o = 16; o; o >>= 1) s0 += __shfl_xor_sync(0xffffffffu, s0, o);
        if (lane == 0) red[wid][h] = s0;
    }
    __syncthreads();
#pragma unroll
    for (int h = 0; h < 12; h++) {
        float s0 = red[0][h];
#pragma unroll
        for (int w = 1; w < 8; w++) s0 += red[w][h];
        float rinv = 1.f / s0;
        ull r2 = pack2(rinv, rinv);
        mul2(m2[h][0], m2[h][0], r2);
        mul2(m2[h][1], m2[h][1], r2);
    }

#pragma unroll
    for (int g = 0; g < 12; g++) {
        ull o0 = pack2(bwv[g], bwv[g]);
        ull o1 = o0;
#pragma unroll
        for (int h = 0; h < 12; h++) {
            ull w = ww2[g * 12 + h];
            fma2(o0, w, m2[h][0]);
            fma2(o1, w, m2[h][1]);
        }
        float2 f0 = unpack2(o0), f1 = unpack2(o1);
        uint2 u;
        *(__half2*)&u.x = __floats2half2_rn(f0.x, f0.y);
        *(__half2*)&u.y = __floats2half2_rn(f1.x, f1.y);
        *(uint2*)&S[rowbase + (size_t)g * NTNT + j0] = u;
    }
}

// ============================================================
// av_f16: per (b,h): O(1024x64) = P(1024x1024) @ V(1024x64),
// fp16 MMA + ldmatrix, fp16 O. 64x64 tile, BK=32,
// 4-stage cp.async (wait 2), 256 thr.
// ============================================================
__global__ __launch_bounds__(256, 4) void av_f16(
    const __half* __restrict__ P, const __half* __restrict__ Vt,
    __half* __restrict__ O)
{
    extern __shared__ float sm[];
    __half* Ps = (__half*)sm;            // [4][64][40]
    __half* Vs = Ps + 4 * 2560;          // [4][64][40]

    int bh = blockIdx.y;
    int b = bh / NH, h = bh % NH;
    const __half* Pg = P + (size_t)bh * NTNT + (size_t)blockIdx.x * 64 * NT;
    const __half* Vg = Vt + (size_t)bh * HD * NT;   // [d][tok]

    int tid = threadIdx.x, lane = tid & 31, wid = tid >> 5;
    int lr = lane >> 2, lc = lane & 3;
    int m0 = (wid & 3) * 16, n0 = (wid >> 2) * 32;

    int aRow = lane & 15;
    int aK   = (lane >> 4) * 8;
    int mat  = lane >> 3;
    int bRow = (mat >> 1) * 8 + (lane & 7);
    int bK   = (mat & 1) * 8;

    int ldr = tid >> 2, ldc = (tid & 3) * 8;

#define AV_LOAD(s, k0) do {                                             \
    __half* Pd = Ps + (s) * 2560;                                       \
    __half* Vd = Vs + (s) * 2560;                                       \
    cp16(&Pd[ldr * 40 + ldc], Pg + (size_t)ldr * NT + (k0) + ldc);      \
    cp16(&Vd[ldr * 40 + ldc], Vg + (size_t)ldr * NT + (k0) + ldc);      \
    CP_COMMIT;                                                          \
} while (0)

    AV_LOAD(0, 0);
    AV_LOAD(1, 32);
    AV_LOAD(2, 64);

    float acc[4][4] = {};
    const int NITER = NT / 32;   // 32
    for (int it = 0; it < NITER; it++) {
        CP_WAIT2;
        __syncthreads();
        int s = it % 4;
        unsigned qa = (unsigned)__cvta_generic_to_shared(Ps + s * 2560);
        unsigned qb = (unsigned)__cvta_generic_to_shared(Vs + s * 2560);
#pragma unroll
        for (int kk = 0; kk < 32; kk += 16) {
            unsigned a0, a1, a2, a3;
            unsigned ad = qa + ((m0 + aRow) * 40 + kk + aK) * 2;
            ldsm4(a0, a1, a2, a3, ad);
            unsigned b[4][2];
#pragma unroll
            for (int p = 0; p < 2; p++) {
                unsigned bd = qb + ((n0 + p * 16 + bRow) * 40 + kk + bK) * 2;
                ldsm4(b[2*p][0], b[2*p][1], b[2*p+1][0], b[2*p+1][1], bd);
            }
#pragma unroll
            for (int ni = 0; ni < 4; ni++)
                mma16h(acc[ni], a0, a1, a2, a3, b[ni][0], b[ni][1]);
        }
        __syncthreads();
        if (it + 3 < NITER) AV_LOAD((it + 3) % 4, (it + 3) * 32);
        else CP_COMMIT;
    }
#undef AV_LOAD

#pragma unroll
    for (int ni = 0; ni < 4; ni++) {
        int col = n0 + ni * 8 + 2 * lc;
#pragma unroll
        for (int half_ = 0; half_ < 2; half_++) {
            int row = blockIdx.x * 64 + m0 + lr + half_ * 8;
            *(__half2*)&O[(size_t)(b * NT + row) * DIMC + h * HD + col] =
                __floats2half2_rn(acc[ni][half_*2], acc[ni][half_*2 + 1]);
        }
    }
}

// ============================================================
extern "C" void kernel_launch(void* const* d_in, const int* in_sizes, int n_in,
                              void* d_out, int out_size)
{
    const float* x  = (const float*)d_in[0];
    const float* Wq = (const float*)d_in[1];
    const float* Wk = (const float*)d_in[2];
    const float* Wv = (const float*)d_in[3];
    const float* Wl = (const float*)d_in[4];
    const float* bl = (const float*)d_in[5];
    const float* Ww = (const float*)d_in[6];
    const float* bw = (const float*)d_in[7];
    const float* Wp = (const float*)d_in[8];
    const float* bp = (const float*)d_in[9];
    float* out = (float*)d_out;

    __half *gxh, *gwt, *gq, *gk, *gvt, *gS, *gOh;
    cudaGetSymbolAddress((void**)&gxh, g_xh);
    cudaGetSymbolAddress((void**)&gwt, g_wt);
    cudaGetSymbolAddress((void**)&gq, g_q);
    cudaGetSymbolAddress((void**)&gk, g_k);
    cudaGetSymbolAddress((void**)&gvt, g_vt);
    cudaGetSymbolAddress((void**)&gS, g_S);
    cudaGetSymbolAddress((void**)&gOh, g_Oh);

    int qkv_smem = 4 * 2 * 5120 * (int)sizeof(__half);               // 81920
    cudaFuncSetAttribute(qkv_f16,
                         cudaFuncAttributeMaxDynamicSharedMemorySize, qkv_smem);
    cudaFuncSetAttribute(outproj_f16,
                         cudaFuncAttributeMaxDynamicSharedMemorySize, qkv_smem);
    int score_smem = 2 * 128 * 72 * (int)sizeof(__half);             // 36864
    cudaFuncSetAttribute(score_f16,
                         cudaFuncAttributeMaxDynamicSharedMemorySize, score_smem);
    int av_smem = 4 * 2 * 2560 * (int)sizeof(__half);                // 40960
    cudaFuncSetAttribute(av_f16,
                         cudaFuncAttributeMaxDynamicSharedMemorySize, av_smem);

    // fp16 conversions (x + 4 weight matrices)
    conv_x<<<M_TOK * DIMC / 1024, 256>>>(x, gxh);
    conv_wt<<<dim3(24, 24, 4), 256>>>(Wq, Wk, Wv, Wp, gwt);

    // QKV projections (fp16), one launch; Q pre-scaled; V fp16 transposed
    qkv_f16<<<dim3(6, 64, 3), 256, qkv_smem>>>(gxh, gwt, gq, gk, gvt);

    // raw scores S = Q K^T -> fp16 (scalar frags), coalesced staged stores
    score_f16<<<dim3(8, 8, 96), 256, score_smem>>>(gq, gk, gS);

    // register-resident fused pre-mix + softmax + post-mix (FFMA2, h-outer)
    softmax_mix_reg<<<dim3(1024, 8), 256>>>(gS, Wl, bl, Ww, bw);

    // attn @ V -> [tok, dim] fp16 (ldmatrix, 4-stage)
    av_f16<<<dim3(16, 96), 256, av_smem>>>(gS, gvt, gOh);

    // final projection + bias (fp16 GEMM, fp32 accum/out, 4-stage)
    outproj_f16<<<dim3(6, 64), 256, qkv_smem>>>(gOh, gwt, out, bp);
}

// round 17
// speedup vs baseline: 1.0077x; 1.0077x over previous
#include <cuda_runtime.h>
#include <cuda_fp16.h>
#include <math.h>

#define DIMC 768
#define NH 12
#define HD 64
#define NB 8
#define NT 1024
#define M_TOK (NB*NT)   // 8192
#define NTNT (NT*NT)

// ---- scratch (device globals: no allocations allowed) ----
__device__ __half g_xh[M_TOK*DIMC];            // x in fp16
__device__ __half g_wt[4*DIMC*DIMC];           // Wq,Wk,Wv,Wp fp16 TRANSPOSED [n][k]
__device__ __half g_q[NB*NH*NT*HD];            // [b,h,n,d] fp16, Q pre-scaled
__device__ __half g_k[NB*NH*NT*HD];            // [b,h,n,d] fp16
__device__ __half g_vt[NB*NH*HD*NT];           // [b,h,d,tok] fp16 (transposed V)
__device__ __half g_S[(size_t)NB*NH*NT*NT];    // scores / probs fp16 (in place)
__device__ __half g_Oh[(size_t)M_TOK*DIMC];    // [tok, dim] fp16

// ---------- helpers ----------
__device__ __forceinline__ void mma16h(float* d, unsigned a0, unsigned a1,
                                       unsigned a2, unsigned a3,
                                       unsigned b0, unsigned b1) {
    asm volatile(
        "mma.sync.aligned.m16n8k16.row.col.f32.f16.f16.f32 "
        "{%0,%1,%2,%3},{%4,%5,%6,%7},{%8,%9},{%0,%1,%2,%3};"
        : "+f"(d[0]), "+f"(d[1]), "+f"(d[2]), "+f"(d[3])
        : "r"(a0), "r"(a1), "r"(a2), "r"(a3), "r"(b0), "r"(b1));
}
__device__ __forceinline__ void ldsm4(unsigned& r0, unsigned& r1,
                                      unsigned& r2, unsigned& r3, unsigned sa) {
    asm volatile("ldmatrix.sync.aligned.m8n8.x4.shared.b16 {%0,%1,%2,%3}, [%4];"
                 : "=r"(r0), "=r"(r1), "=r"(r2), "=r"(r3) : "r"(sa));
}
__device__ __forceinline__ void cp16(void* s, const void* g) {
    unsigned sa = (unsigned)__cvta_generic_to_shared(s);
    asm volatile("cp.async.ca.shared.global [%0], [%1], 16;" :: "r"(sa), "l"(g));
}
#define CP_COMMIT asm volatile("cp.async.commit_group;")
#define CP_WAIT2  asm volatile("cp.async.wait_group 2;")
#define CP_WAIT0  asm volatile("cp.async.wait_group 0;")

// packed f32x2 (FFMA2) helpers — bit-identical to two scalar fmaf's
typedef unsigned long long ull;
__device__ __forceinline__ ull pack2(float lo, float hi) {
    ull r; asm("mov.b64 %0, {%1, %2};" : "=l"(r) : "f"(lo), "f"(hi)); return r;
}
__device__ __forceinline__ float2 unpack2(ull v) {
    float2 f; asm("mov.b64 {%0, %1}, %2;" : "=f"(f.x), "=f"(f.y) : "l"(v)); return f;
}
__device__ __forceinline__ void fma2(ull& d, ull a, ull b) {
    asm("fma.rn.f32x2 %0, %1, %2, %0;" : "+l"(d) : "l"(a), "l"(b));
}
__device__ __forceinline__ void mul2(ull& d, ull a, ull b) {
    asm("mul.rn.f32x2 %0, %1, %2;" : "=l"(d) : "l"(a), "l"(b));
}

// ============================================================
// conversion kernels
// ============================================================
__global__ __launch_bounds__(256) void conv_x(
    const float* __restrict__ x, __half* __restrict__ xh)
{
    int i = (blockIdx.x * 256 + threadIdx.x) * 4;
    float4 v = *(const float4*)&x[i];
    *(__half2*)&xh[i]     = __floats2half2_rn(v.x, v.y);
    *(__half2*)&xh[i + 2] = __floats2half2_rn(v.z, v.w);
}

// transpose+convert: out[n][k] = in[k][n], 32x32 tiles, z selects W
__global__ __launch_bounds__(256) void conv_wt(
    const float* __restrict__ Wq, const float* __restrict__ Wk,
    const float* __restrict__ Wv, const float* __restrict__ Wp,
    __half* __restrict__ Wt)
{
    __shared__ float t[32][33];
    int z = blockIdx.z;
    const float* W = (z == 0) ? Wq : (z == 1) ? Wk : (z == 2) ? Wv : Wp;
    __half* out = Wt + (size_t)z * DIMC * DIMC;
    int n0 = blockIdx.x * 32, k0 = blockIdx.y * 32;
    int tx = threadIdx.x & 31, ty = threadIdx.x >> 5;   // 32 x 8
#pragma unroll
    for (int i = ty; i < 32; i += 8)
        t[i][tx] = W[(size_t)(k0 + i) * DIMC + n0 + tx];
    __syncthreads();
#pragma unroll
    for (int i = ty; i < 32; i += 8)
        out[(size_t)(n0 + i) * DIMC + k0 + tx] = __float2half(t[tx][i]);
}

// ============================================================
// fp16 GEMM body: C[8192,768] = A @ Bm^T (Bm is [n][k] fp16).
// 128x128 tile, BK=32, 4-stage cp.async (wait 2), 256 thr,
// warp 64x32, ldmatrix fragments, SINGLE sync per iteration.
// MODE 1: head-split fp16 [b,h,n,d] (scale).
// MODE 2: transposed fp16 V [b,h,d,tok] via smem staging.
// MODE 3: plain fp32 out + bias.
// ============================================================
template<int MODE>
__device__ __forceinline__ void projh_body(
    const __half* __restrict__ A, const __half* __restrict__ Bm,
    float* __restrict__ Cf, __half* __restrict__ Ch,
    const float* __restrict__ bias, float scale)
{
    extern __shared__ float smf[];
    __half* As = (__half*)smf;        // [4][128][40]
    __half* Bs = As + 4 * 5120;       // [4][128][40]

    int tid = threadIdx.x, lane = tid & 31, wid = tid >> 5;
    int warp_m = wid & 1, warp_n = wid >> 1;
    int rowBase = blockIdx.y * 128, colBase = blockIdx.x * 128;
    int lr = lane >> 2, lc = lane & 3;
    int m0 = warp_m * 64, n0 = warp_n * 32;

    // ldmatrix per-lane addressing (half units)
    int aRow = lane & 15;
    int aK   = (lane >> 4) * 8;
    int mat  = lane >> 3;
    int bRow = (mat >> 1) * 8 + (lane & 7);
    int bK   = (mat & 1) * 8;

    const __half* Ap = A + (size_t)rowBase * DIMC;
    const __half* Bp = Bm + (size_t)colBase * DIMC;

#define QKV_LOAD(s, k0) do {                                            \
    __half* Ad = As + (s) * 5120;                                       \
    __half* Bd = Bs + (s) * 5120;                                       \
    _Pragma("unroll")                                                   \
    for (int i_ = 0; i_ < 2; i_++) {                                    \
        int t_ = tid + i_ * 256;                                        \
        int r_ = t_ >> 2, c_ = (t_ & 3) * 8;                            \
        cp16(&Ad[r_ * 40 + c_], Ap + (size_t)r_ * DIMC + (k0) + c_);    \
        cp16(&Bd[r_ * 40 + c_], Bp + (size_t)r_ * DIMC + (k0) + c_);    \
    }                                                                   \
    CP_COMMIT;                                                          \
} while (0)

    QKV_LOAD(0, 0);
    QKV_LOAD(1, 32);
    QKV_LOAD(2, 64);

    float acc[4][4][4] = {};
    const int NITER = DIMC / 32;   // 24
    for (int it = 0; it < NITER; it++) {
        CP_WAIT2;
        __syncthreads();
        // issue next tile BEFORE compute (writes stage (it-1)%4, whose
        // readers all passed the sync above) — one barrier per iteration
        if (it + 3 < NITER) QKV_LOAD((it + 3) % 4, (it + 3) * 32);
        else CP_COMMIT;
        int s = it % 4;
        unsigned qa = (unsigned)__cvta_generic_to_shared(As + s * 5120);
        unsigned qb = (unsigned)__cvta_generic_to_shared(Bs + s * 5120);
#pragma unroll
        for (int kk = 0; kk < 32; kk += 16) {
            unsigned a[4][4], b[4][2];
#pragma unroll
            for (int mi = 0; mi < 4; mi++) {
                unsigned ad = qa + ((m0 + mi * 16 + aRow) * 40 + kk + aK) * 2;
                ldsm4(a[mi][0], a[mi][1], a[mi][2], a[mi][3], ad);
            }
#pragma unroll
            for (int p = 0; p < 2; p++) {
                unsigned bd = qb + ((n0 + p * 16 + bRow) * 40 + kk + bK) * 2;
                ldsm4(b[2*p][0], b[2*p][1], b[2*p+1][0], b[2*p+1][1], bd);
            }
#pragma unroll
            for (int mi = 0; mi < 4; mi++)
#pragma unroll
                for (int ni = 0; ni < 4; ni++)
                    mma16h(acc[mi][ni], a[mi][0], a[mi][1], a[mi][2], a[mi][3],
                           b[ni][0], b[ni][1]);
        }
    }
#undef QKV_LOAD
    __syncthreads();

    if (MODE == 2) {
        // stage transposed fp16 tile: stg[local_col][local_row], stride 136
        __half* stg = (__half*)smf;   // 34816 B
#pragma unroll
        for (int mi = 0; mi < 4; mi++) {
#pragma unroll
            for (int ni = 0; ni < 4; ni++) {
                int col = n0 + ni * 8 + 2 * lc;
#pragma unroll
                for (int half_ = 0; half_ < 2; half_++) {
                    int row = m0 + mi * 16 + lr + half_ * 8;
                    stg[col * 136 + row]       = __float2half(acc[mi][ni][half_*2 + 0]);
                    stg[(col + 1) * 136 + row] = __float2half(acc[mi][ni][half_*2 + 1]);
                }
            }
        }
        __syncthreads();
        int b_ = rowBase >> 10;
        int rloc = rowBase & 1023;
        for (int t = tid; t < 128 * 16; t += 256) {
            int col = t >> 4;
            int r8 = (t & 15) * 8;
            int gcol = colBase + col;
            int hh = gcol >> 6, d = gcol & 63;
            size_t dst = ((size_t)(b_ * NH + hh) * HD + d) * NT + rloc + r8;
            *(uint4*)&Ch[dst] = *(const uint4*)&stg[col * 136 + r8];
        }
        return;
    }

#pragma unroll
    for (int mi = 0; mi < 4; mi++) {
#pragma unroll
        for (int ni = 0; ni < 4; ni++) {
            int col = colBase + n0 + ni * 8 + 2 * lc;
            float bv0 = 0.f, bv1 = 0.f;
            if (MODE == 3) { bv0 = bias[col]; bv1 = bias[col + 1]; }
#pragma unroll
            for (int half_ = 0; half_ < 2; half_++) {
                int row = rowBase + m0 + mi * 16 + lr + half_ * 8;
                if (MODE == 3) {
                    *(float2*)&Cf[(size_t)row * DIMC + col] =
                        make_float2(acc[mi][ni][half_*2 + 0] + bv0,
                                    acc[mi][ni][half_*2 + 1] + bv1);
                } else {    // MODE 1: fp16 head-split [b,h,n,d]
                    int b_ = row >> 10, rr = row & 1023;
                    int h = col >> 6, d = col & 63;
                    *(__half2*)&Ch[(((size_t)(b_ * NH + h) * NT + rr) * HD + d)] =
                        __floats2half2_rn(acc[mi][ni][half_*2 + 0] * scale,
                                          acc[mi][ni][half_*2 + 1] * scale);
                }
            }
        }
    }
}

__global__ __launch_bounds__(256, 2) void qkv_f16(
    const __half* __restrict__ xh, const __half* __restrict__ Wt,
    __half* __restrict__ q, __half* __restrict__ k, __half* __restrict__ vt)
{
    int z = blockIdx.z;
    const __half* Bm = Wt + (size_t)z * DIMC * DIMC;
    if (z == 0)      projh_body<1>(xh, Bm, nullptr, q, nullptr, 0.125f);
    else if (z == 1) projh_body<1>(xh, Bm, nullptr, k, nullptr, 1.0f);
    else             projh_body<2>(xh, Bm, nullptr, vt, nullptr, 1.0f);
}

__global__ __launch_bounds__(256, 2) void outproj_f16(
    const __half* __restrict__ Oh, const __half* __restrict__ Wt,
    float* __restrict__ C, const float* __restrict__ bias)
{
    projh_body<3>(Oh, Wt + (size_t)3 * DIMC * DIMC, C, nullptr, bias, 1.0f);
}

// ============================================================
// score_f16: per (b,h): S = Q(1024x64) @ K^T, fp16 MMA,
// scalar fragment loads. 128x64 tile, 4 CTAs/SM, whole K=64
// in smem. Staged coalesced fp16 epilogue.
// ============================================================
__global__ __launch_bounds__(256, 4) void score_f16(
    const __half* __restrict__ Q, const __half* __restrict__ Kp,
    __half* __restrict__ S)
{
    extern __shared__ float smf[];
    __half* Qs = (__half*)smf;        // [128][72]
    __half* Ks = Qs + 128 * 72;       // [64][72]

    int bh = blockIdx.z;
    const __half* Qg = Q + (size_t)bh * NT * HD + (size_t)blockIdx.y * 128 * HD;
    const __half* Kg = Kp + (size_t)bh * NT * HD + (size_t)blockIdx.x * 64 * HD;

    int tid = threadIdx.x, lane = tid & 31, wid = tid >> 5;
    int lr = lane >> 2, lc = lane & 3;
    int warp_m = wid & 3, warp_n = wid >> 2;
    int m0 = warp_m * 32, n0 = warp_n * 32;

#pragma unroll
    for (int i = 0; i < 4; i++) {
        int t = tid + i * 256;
        int r = t >> 3, c = (t & 7) * 8;
        cp16(&Qs[r * 72 + c], Qg + (size_t)r * HD + c);
    }
#pragma unroll
    for (int i = 0; i < 2; i++) {
        int t = tid + i * 256;
        int r = t >> 3, c = (t & 7) * 8;
        cp16(&Ks[r * 72 + c], Kg + (size_t)r * HD + c);
    }
    CP_COMMIT;
    CP_WAIT0;
    __syncthreads();

    float acc[2][4][4] = {};
#pragma unroll
    for (int kk = 0; kk < 64; kk += 16) {
        unsigned a[2][4], b[4][2];
#pragma unroll
        for (int mi = 0; mi < 2; mi++) {
            int rb = (m0 + mi * 16 + lr) * 72 + kk + 2 * lc;
            a[mi][0] = *(const unsigned*)&Qs[rb];
            a[mi][1] = *(const unsigned*)&Qs[rb + 8 * 72];
            a[mi][2] = *(const unsigned*)&Qs[rb + 8];
            a[mi][3] = *(const unsigned*)&Qs[rb + 8 * 72 + 8];
        }
#pragma unroll
        for (int ni = 0; ni < 4; ni++) {
            int nb = (n0 + ni * 8 + lr) * 72 + kk + 2 * lc;
            b[ni][0] = *(const unsigned*)&Ks[nb];
            b[ni][1] = *(const unsigned*)&Ks[nb + 8];
        }
#pragma unroll
        for (int mi = 0; mi < 2; mi++)
#pragma unroll
            for (int ni = 0; ni < 4; ni++)
                mma16h(acc[mi][ni], a[mi][0], a[mi][1], a[mi][2], a[mi][3],
                       b[ni][0], b[ni][1]);
    }

    // stage fp16 tile (128x64) in smem, stride 72, then uint4 flush
    __syncthreads();
    __half* stg = (__half*)smf;   // [128][72] halves = 18432 B
#pragma unroll
    for (int mi = 0; mi < 2; mi++) {
#pragma unroll
        for (int ni = 0; ni < 4; ni++) {
            int c = n0 + ni * 8 + 2 * lc;
#pragma unroll
            for (int half_ = 0; half_ < 2; half_++) {
                int r = m0 + mi * 16 + lr + half_ * 8;
                *(__half2*)&stg[r * 72 + c] =
                    __floats2half2_rn(acc[mi][ni][half_*2], acc[mi][ni][half_*2 + 1]);
            }
        }
    }
    __syncthreads();

    __half* Sg = S + (size_t)bh * NTNT +
                 (size_t)(blockIdx.y * 128) * NT + blockIdx.x * 64;
#pragma unroll
    for (int i = 0; i < 4; i++) {
        int t = tid + i * 256;
        int r = t >> 3, c8 = (t & 7) * 8;
        *(uint4*)&Sg[(size_t)r * NT + c8] = *(const uint4*)&stg[r * 72 + c8];
    }
}

// ============================================================
// softmax_mix_reg: register-resident talking-heads softmax,
// FFMA2 h-outer. 1 row/CTA, 256 thr, 4 j-cols/thread.
// ============================================================
__global__ __launch_bounds__(256, 2) void softmax_mix_reg(
    __half* __restrict__ S, const float* __restrict__ Wl,
    const float* __restrict__ bl, const float* __restrict__ Ww,
    const float* __restrict__ bw)
{
    __shared__ ull wl2[144], ww2[144];
    __shared__ float blv[12], bwv[12];
    __shared__ float red[8][12];

    int tid = threadIdx.x, lane = tid & 31, wid = tid >> 5;
    int i = blockIdx.x, b = blockIdx.y;
    if (tid < 144) {
        float a = Wl[tid]; wl2[tid] = pack2(a, a);
        float c = Ww[tid]; ww2[tid] = pack2(c, c);
    }
    if (tid < 12)  { blv[tid] = bl[tid]; bwv[tid] = bw[tid]; }
    __syncthreads();

    size_t rowbase = (size_t)b * NH * NTNT + (size_t)i * NT;
    int j0 = tid * 4;

    uint2 raw[12];
#pragma unroll
    for (int h = 0; h < 12; h++)
        raw[h] = *(const uint2*)&S[rowbase + (size_t)h * NTNT + j0];

    ull m2[12][2];
#pragma unroll
    for (int g = 0; g < 12; g++) {
        ull b2 = pack2(blv[g], blv[g]);
        m2[g][0] = b2; m2[g][1] = b2;
    }
#pragma unroll
    for (int h = 0; h < 12; h++) {
        float2 f0 = __half22float2(*(__half2*)&raw[h].x);
        float2 f1 = __half22float2(*(__half2*)&raw[h].y);
        ull s0 = pack2(f0.x, f0.y);
        ull s1 = pack2(f1.x, f1.y);
#pragma unroll
        for (int g = 0; g < 12; g++) {
            ull w = wl2[g * 12 + h];
            fma2(m2[g][0], w, s0);
            fma2(m2[g][1], w, s1);
        }
    }

#pragma unroll
    for (int h = 0; h < 12; h++) {
        float2 a0 = unpack2(m2[h][0]), a1 = unpack2(m2[h][1]);
        float a = fmaxf(fmaxf(a0.x, a0.y), fmaxf(a1.x, a1.y));
#pragma unroll
        for (int o = 16; o; o >>= 1) a = fmaxf(a, __shfl_xor_sync(0xffffffffu, a, o));
        if (lane == 0) red[wid][h] = a;
    }
    __syncthreads();
    float mxv[12];
#pragma unroll
    for (int h = 0; h < 12; h++) {
        float a = red[0][h];
#pragma unroll
        for (int w = 1; w < 8; w++) a = fmaxf(a, red[w][h]);
        mxv[h] = a;
    }
    __syncthreads();

#pragma unroll
    for (int h = 0; h < 12; h++) {
        float2 a0 = unpack2(m2[h][0]), a1 = unpack2(m2[h][1]);
        float e0 = __expf(a0.x - mxv[h]);
        float e1 = __expf(a0.y - mxv[h]);
        float e2 = __expf(a1.x - mxv[h]);
        float e3 = __expf(a1.y - mxv[h]);
        m2[h][0] = pack2(e0, e1);
        m2[h][1] = pack2(e2, e3);
        float s0 = (e0 + e1) + (e2 + e3);
#pragma unroll
        for (int o = 16; o; o >>= 1) s0 += __shfl_xor_sync(0xffffffffu, s0, o);
        if (lane == 0) red[wid][h] = s0;
    }
    __syncthreads();
#pragma unroll
    for (int h = 0; h < 12; h++) {
        float s0 = red[0][h];
#pragma unroll
        for (int w = 1; w < 8; w++) s0 += red[w][h];
        float rinv = 1.f / s0;
        ull r2 = pack2(rinv, rinv);
        mul2(m2[h][0], m2[h][0], r2);
        mul2(m2[h][1], m2[h][1], r2);
    }

#pragma unroll
    for (int g = 0; g < 12; g++) {
        ull o0 = pack2(bwv[g], bwv[g]);
        ull o1 = o0;
#pragma unroll
        for (int h = 0; h < 12; h++) {
            ull w = ww2[g * 12 + h];
            fma2(o0, w, m2[h][0]);
            fma2(o1, w, m2[h][1]);
        }
        float2 f0 = unpack2(o0), f1 = unpack2(o1);
        uint2 u;
        *(__half2*)&u.x = __floats2half2_rn(f0.x, f0.y);
        *(__half2*)&u.y = __floats2half2_rn(f1.x, f1.y);
        *(uint2*)&S[rowbase + (size_t)g * NTNT + j0] = u;
    }
}

// ============================================================
// av_f16: per (b,h): O(1024x64) = P(1024x1024) @ V(1024x64),
// fp16 MMA + ldmatrix, fp16 O. 64x64 tile, BK=32,
// 4-stage cp.async (wait 2), SINGLE sync per iteration.
// ============================================================
__global__ __launch_bounds__(256, 4) void av_f16(
    const __half* __restrict__ P, const __half* __restrict__ Vt,
    __half* __restrict__ O)
{
    extern __shared__ float sm[];
    __half* Ps = (__half*)sm;            // [4][64][40]
    __half* Vs = Ps + 4 * 2560;          // [4][64][40]

    int bh = blockIdx.y;
    int b = bh / NH, h = bh % NH;
    const __half* Pg = P + (size_t)bh * NTNT + (size_t)blockIdx.x * 64 * NT;
    const __half* Vg = Vt + (size_t)bh * HD * NT;   // [d][tok]

    int tid = threadIdx.x, lane = tid & 31, wid = tid >> 5;
    int lr = lane >> 2, lc = lane & 3;
    int m0 = (wid & 3) * 16, n0 = (wid >> 2) * 32;

    int aRow = lane & 15;
    int aK   = (lane >> 4) * 8;
    int mat  = lane >> 3;
    int bRow = (mat >> 1) * 8 + (lane & 7);
    int bK   = (mat & 1) * 8;

    int ldr = tid >> 2, ldc = (tid & 3) * 8;

#define AV_LOAD(s, k0) do {                                             \
    __half* Pd = Ps + (s) * 2560;                                       \
    __half* Vd = Vs + (s) * 2560;                                       \
    cp16(&Pd[ldr * 40 + ldc], Pg + (size_t)ldr * NT + (k0) + ldc);      \
    cp16(&Vd[ldr * 40 + ldc], Vg + (size_t)ldr * NT + (k0) + ldc);      \
    CP_COMMIT;                                                          \
} while (0)

    AV_LOAD(0, 0);
    AV_LOAD(1, 32);
    AV_LOAD(2, 64);

    float acc[4][4] = {};
    const int NITER = NT / 32;   // 32
    for (int it = 0; it < NITER; it++) {
        CP_WAIT2;
        __syncthreads();
        if (it + 3 < NITER) AV_LOAD((it + 3) % 4, (it + 3) * 32);
        else CP_COMMIT;
        int s = it % 4;
        unsigned qa = (unsigned)__cvta_generic_to_shared(Ps + s * 2560);
        unsigned qb = (unsigned)__cvta_generic_to_shared(Vs + s * 2560);
#pragma unroll
        for (int kk = 0; kk < 32; kk += 16) {
            unsigned a0, a1, a2, a3;
            unsigned ad = qa + ((m0 + aRow) * 40 + kk + aK) * 2;
            ldsm4(a0, a1, a2, a3, ad);
            unsigned b[4][2];
#pragma unroll
            for (int p = 0; p < 2; p++) {
                unsigned bd = qb + ((n0 + p * 16 + bRow) * 40 + kk + bK) * 2;
                ldsm4(b[2*p][0], b[2*p][1], b[2*p+1][0], b[2*p+1][1], bd);
            }
#pragma unroll
            for (int ni = 0; ni < 4; ni++)
                mma16h(acc[ni], a0, a1, a2, a3, b[ni][0], b[ni][1]);
        }
    }
#undef AV_LOAD

#pragma unroll
    for (int ni = 0; ni < 4; ni++) {
        int col = n0 + ni * 8 + 2 * lc;
#pragma unroll
        for (int half_ = 0; half_ < 2; half_++) {
            int row = blockIdx.x * 64 + m0 + lr + half_ * 8;
            *(__half2*)&O[(size_t)(b * NT + row) * DIMC + h * HD + col] =
                __floats2half2_rn(acc[ni][half_*2], acc[ni][half_*2 + 1]);
        }
    }
}

// ============================================================
extern "C" void kernel_launch(void* const* d_in, const int* in_sizes, int n_in,
                              void* d_out, int out_size)
{
    const float* x  = (const float*)d_in[0];
    const float* Wq = (const float*)d_in[1];
    const float* Wk = (const float*)d_in[2];
    const float* Wv = (const float*)d_in[3];
    const float* Wl = (const float*)d_in[4];
    const float* bl = (const float*)d_in[5];
    const float* Ww = (const float*)d_in[6];
    const float* bw = (const float*)d_in[7];
    const float* Wp = (const float*)d_in[8];
    const float* bp = (const float*)d_in[9];
    float* out = (float*)d_out;

    __half *gxh, *gwt, *gq, *gk, *gvt, *gS, *gOh;
    cudaGetSymbolAddress((void**)&gxh, g_xh);
    cudaGetSymbolAddress((void**)&gwt, g_wt);
    cudaGetSymbolAddress((void**)&gq, g_q);
    cudaGetSymbolAddress((void**)&gk, g_k);
    cudaGetSymbolAddress((void**)&gvt, g_vt);
    cudaGetSymbolAddress((void**)&gS, g_S);
    cudaGetSymbolAddress((void**)&gOh, g_Oh);

    int qkv_smem = 4 * 2 * 5120 * (int)sizeof(__half);               // 81920
    cudaFuncSetAttribute(qkv_f16,
                         cudaFuncAttributeMaxDynamicSharedMemorySize, qkv_smem);
    cudaFuncSetAttribute(outproj_f16,
                         cudaFuncAttributeMaxDynamicSharedMemorySize, qkv_smem);
    int score_smem = (128 * 72 + 64 * 72) * (int)sizeof(__half);     // 27648
    cudaFuncSetAttribute(score_f16,
                         cudaFuncAttributeMaxDynamicSharedMemorySize, score_smem);
    int av_smem = 4 * 2 * 2560 * (int)sizeof(__half);                // 40960
    cudaFuncSetAttribute(av_f16,
                         cudaFuncAttributeMaxDynamicSharedMemorySize, av_smem);

    // fp16 conversions (x + 4 weight matrices)
    conv_x<<<M_TOK * DIMC / 1024, 256>>>(x, gxh);
    conv_wt<<<dim3(24, 24, 4), 256>>>(Wq, Wk, Wv, Wp, gwt);

    // QKV projections (fp16), one launch; Q pre-scaled; V fp16 transposed
    qkv_f16<<<dim3(6, 64, 3), 256, qkv_smem>>>(gxh, gwt, gq, gk, gvt);

    // raw scores S = Q K^T -> fp16 (128x64 tiles, 4 CTAs/SM)
    score_f16<<<dim3(16, 8, 96), 256, score_smem>>>(gq, gk, gS);

    // register-resident fused pre-mix + softmax + post-mix (FFMA2, h-outer)
    softmax_mix_reg<<<dim3(1024, 8), 256>>>(gS, Wl, bl, Ww, bw);

    // attn @ V -> [tok, dim] fp16 (ldmatrix, single-sync pipeline)
    av_f16<<<dim3(16, 96), 256, av_smem>>>(gS, gvt, gOh);

    // final projection + bias (fp16 GEMM, fp32 accum/out, single-sync)
    outproj_f16<<<dim3(6, 64), 256, qkv_smem>>>(gOh, gwt, out, bp);
}